// round 6
// baseline (speedup 1.0000x reference)
#include <cuda_runtime.h>
#include <cuda_bf16.h>
#include <cstdint>

// NPSCalculator: nps = sum_{b,h,w} min_k sqrt( sum_c (x[b,c,h,w] - p[k,c] + 1e-6)^2 + 1e-6 ) / size
// B=8, C=3, H=512, W=512, NUM_COLORS=30.
//
// R6: occupancy attack. R5 evidence: no pipe >45%, issue=44%, occ=40% -- and 64 regs x
// 128 thr x 8 blocks = the ENTIRE 64K regfile: 50% occ is a hard cap at 64 regs.
// Fix: 4 px/thread (~42 regs) + launch_bounds(128,12) -> 48 warps/SM (75%).
//  - color loop start rotated per warp (min is order-independent) to spread LDS traffic.
//  - dist^2 = ssq_pixel + (2v)·x + sum v^2 ; min over colors; MUFU-free packed sqrt.
//  - single launch: per-block partials + wrap-around atomicInc last-block reduce.

#define HW_       262144
#define CHW_      (3 * HW_)
#define THREADS_  128
#define BLOCKS_   4096
#define INV_SIZE_ (1.0f / 6291456.0f)

typedef unsigned long long u64;

__device__ float        g_partial[BLOCKS_];
__device__ unsigned int g_count = 0;

__device__ __forceinline__ u64 f2pk(float lo, float hi) {
    u64 r; asm("mov.b64 %0, {%1, %2};" : "=l"(r) : "f"(lo), "f"(hi)); return r;
}
__device__ __forceinline__ void f2unpk(u64 v, float& lo, float& hi) {
    asm("mov.b64 {%0, %1}, %2;" : "=f"(lo), "=f"(hi) : "l"(v));
}
__device__ __forceinline__ u64 fma2(u64 a, u64 b, u64 c) {
    u64 r; asm("fma.rn.f32x2 %0, %1, %2, %3;" : "=l"(r) : "l"(a), "l"(b), "l"(c)); return r;
}
__device__ __forceinline__ u64 mul2(u64 a, u64 b) {
    u64 r; asm("mul.rn.f32x2 %0, %1, %2;" : "=l"(r) : "l"(a), "l"(b)); return r;
}
__device__ __forceinline__ u64 add2(u64 a, u64 b) {
    u64 r; asm("add.rn.f32x2 %0, %1, %2;" : "=l"(r) : "l"(a), "l"(b)); return r;
}
// fused: {lo,hi} = a*b + c  (unpack aliased by ptxas)
__device__ __forceinline__ void fma2u(u64 a, u64 b, u64 c, float& lo, float& hi) {
    asm("{\n\t.reg .b64 t;\n\tfma.rn.f32x2 t, %2, %3, %4;\n\tmov.b64 {%0, %1}, t;\n\t}"
        : "=f"(lo), "=f"(hi) : "l"(a), "l"(b), "l"(c));
}

// MUFU-free packed sqrt: magic rsqrt seed + 2 Newton iters + x*r. x in [2e-6, ~13].
__device__ __forceinline__ u64 sqrt2_nomufu(u64 x, u64 C_H, u64 C_1p5) {
    float xl, xh;
    f2unpk(x, xl, xh);
    float rl = __int_as_float(0x5f3759df - (__float_as_int(xl) >> 1));
    float rh = __int_as_float(0x5f3759df - (__float_as_int(xh) >> 1));
    u64 r   = f2pk(rl, rh);
    u64 hxn = mul2(x, C_H);                 // -0.5 * x
    u64 m, u;
    m = mul2(r, r); u = fma2(hxn, m, C_1p5); r = mul2(r, u);   // iter 1
    m = mul2(r, r); u = fma2(hxn, m, C_1p5); r = mul2(r, u);   // iter 2
    return mul2(x, r);
}

__global__ __launch_bounds__(THREADS_, 12)
void nps_kernel(const float* __restrict__ adv,
                const float* __restrict__ prn,
                float* __restrict__ out)
{
    // [k][0] = {W0, W1}, [k][1] = {W2, C};  W_c = 2*(1e-6 - p_kc) dup'd, C = sum v^2 dup'd
    __shared__ ulonglong2 shWC[60];
    __shared__ float      shRed[4];
    __shared__ int        shLast;

    int tid = threadIdx.x;
    if (tid < 30) {
        float v0 = 1e-6f - prn[tid * 3 + 0];
        float v1 = 1e-6f - prn[tid * 3 + 1];
        float v2 = 1e-6f - prn[tid * 3 + 2];
        float c  = v0 * v0 + v1 * v1 + v2 * v2;
        shWC[tid * 2 + 0] = make_ulonglong2(f2pk(2.f * v0, 2.f * v0),
                                            f2pk(2.f * v1, 2.f * v1));
        shWC[tid * 2 + 1] = make_ulonglong2(f2pk(2.f * v2, 2.f * v2),
                                            f2pk(c, c));
    }
    __syncthreads();

    // one float4-group (4 pixels) per thread
    int g  = blockIdx.x * THREADS_ + tid;          // 0 .. 524287
    int p4 = g * 4;
    const float4* q = reinterpret_cast<const float4*>(
        adv + (size_t)(p4 >> 18) * CHW_ + (p4 & (HW_ - 1)));
    float4 a0 = q[0];
    float4 a1 = q[HW_ / 4];
    float4 a2 = q[2 * (HW_ / 4)];

    u64 XA0 = f2pk(a0.x, a0.y), XA1 = f2pk(a1.x, a1.y), XA2 = f2pk(a2.x, a2.y);
    u64 XB0 = f2pk(a0.z, a0.w), XB1 = f2pk(a1.z, a1.w), XB2 = f2pk(a2.z, a2.w);

    const u64 EPS2 = f2pk(1e-6f, 1e-6f);
    // per-pixel sum of squares + 1e-6 (constant over colors)
    u64 sA = fma2(XA0, XA0, EPS2); sA = fma2(XA1, XA1, sA); sA = fma2(XA2, XA2, sA);
    u64 sB = fma2(XB0, XB0, EPS2); sB = fma2(XB1, XB1, sB); sB = fma2(XB2, XB2, sB);

    // rotate the color-loop start per warp: min is order-independent, and this
    // decorrelates the shared-memory fetch stream across the 48 resident warps.
    int k0 = ((tid >> 5) * 7 + (blockIdx.x & 3) * 13) % 30;

    float mA0, mA1, mB0, mB1;
    {   // first color peeled: initializes the mins
        ulonglong2 w01 = shWC[k0 * 2 + 0];
        ulonglong2 w2c = shWC[k0 * 2 + 1];
        u64 aA = fma2(w01.x, XA0, w2c.y);
        u64 aB = fma2(w01.x, XB0, w2c.y);
        aA = fma2(w01.y, XA1, aA); aB = fma2(w01.y, XB1, aB);
        fma2u(w2c.x, XA2, aA, mA0, mA1);
        fma2u(w2c.x, XB2, aB, mB0, mB1);
    }

    #pragma unroll 29
    for (int i = 1; i < 30; i++) {
        int k = k0 + i;
        k = (k >= 30) ? (k - 30) : k;
        ulonglong2 w01 = shWC[k * 2 + 0];
        ulonglong2 w2c = shWC[k * 2 + 1];
        float lo, hi;
        u64 aA = fma2(w01.x, XA0, w2c.y);
        u64 aB = fma2(w01.x, XB0, w2c.y);
        aA = fma2(w01.y, XA1, aA); aB = fma2(w01.y, XB1, aB);
        fma2u(w2c.x, XA2, aA, lo, hi); mA0 = fminf(mA0, lo); mA1 = fminf(mA1, hi);
        fma2u(w2c.x, XB2, aB, lo, hi); mB0 = fminf(mB0, lo); mB1 = fminf(mB1, hi);
    }

    // dist^2 per pixel (packed) = packed mins + packed ssq
    u64 dA = add2(f2pk(mA0, mA1), sA);
    u64 dB = add2(f2pk(mB0, mB1), sB);

    const u64 C_H   = f2pk(-0.5f, -0.5f);
    const u64 C_1p5 = f2pk(1.5f, 1.5f);
    u64 qA = sqrt2_nomufu(dA, C_H, C_1p5);
    u64 qB = sqrt2_nomufu(dB, C_H, C_1p5);

    u64 ts = add2(qA, qB);
    float tl, th;
    f2unpk(ts, tl, th);
    float tsum = tl + th;

    // warp reduce
    #pragma unroll
    for (int off = 16; off > 0; off >>= 1)
        tsum += __shfl_xor_sync(0xffffffffu, tsum, off);
    if ((tid & 31) == 0) shRed[tid >> 5] = tsum;
    __syncthreads();

    if (tid == 0) {
        float bs = shRed[0] + shRed[1] + shRed[2] + shRed[3];
        g_partial[blockIdx.x] = bs;
        __threadfence();
        unsigned int prev = atomicInc(&g_count, BLOCKS_ - 1);
        shLast = (prev == BLOCKS_ - 1);
    }
    __syncthreads();

    if (shLast) {
        volatile float* vp = g_partial;
        float s = 0.0f;
        #pragma unroll
        for (int i = 0; i < BLOCKS_ / THREADS_; i++)
            s += vp[tid + i * THREADS_];
        #pragma unroll
        for (int off = 16; off > 0; off >>= 1)
            s += __shfl_xor_sync(0xffffffffu, s, off);
        if ((tid & 31) == 0) shRed[tid >> 5] = s;
        __syncthreads();
        if (tid == 0)
            out[0] = (shRed[0] + shRed[1] + shRed[2] + shRed[3]) * INV_SIZE_;
    }
}

extern "C" void kernel_launch(void* const* d_in, const int* in_sizes, int n_in,
                              void* d_out, int out_size)
{
    const float* adv = (const float*)d_in[0];   // (8,3,512,512) f32
    const float* prn = (const float*)d_in[1];   // (30,3) f32
    nps_kernel<<<BLOCKS_, THREADS_>>>(adv, prn, (float*)d_out);
}

// round 12
// speedup vs baseline: 1.0864x; 1.0864x over previous
#include <cuda_runtime.h>
#include <cuda_fp16.h>
#include <cuda_bf16.h>
#include <cstdint>

// NPSCalculator: nps = sum_{b,h,w} min_k sqrt( sum_c (x[b,c,h,w] - p[k,c] + 1e-6)^2 + 1e-6 ) / size
// B=8, C=3, H=512, W=512, NUM_COLORS=30.
//
// R9: fp16 ARGMIN + fp32 recompute. R8's all-fp16 value failed (rel_err 1.9e-3) due to
// catastrophic amplification in the expanded form. Fix: fp16 decides WHICH color wins
// (wrong picks only on near-ties -> value error O(sigma^2) ~ 1e-5); the winning color's
// distance is recomputed exactly in fp32 per the reference formula.
//  - hot loop per color per pixel-pair: 3 fma.f16x2 + min.f16x2 + set.eq mask + LOP3 blend.
//  - epilogue per pixel: LDS float4 v-table lookup + 3 FADD + 3 FFMA fp32 + Newton sqrt.
//  - single launch: per-block partials + wrap-around atomicInc last-block reduce.

#define HW_       262144
#define CHW_      (3 * HW_)
#define THREADS_  128
#define BLOCKS_   2048
#define NTHR_     (THREADS_ * BLOCKS_)    // 262144 threads
#define INV_SIZE_ (1.0f / 6291456.0f)

typedef unsigned long long u64;
typedef unsigned int u32;

__device__ float g_partial[BLOCKS_];
__device__ u32   g_count = 0;

// ---- fp32x2 packed helpers ----
__device__ __forceinline__ u64 f2pk(float lo, float hi) {
    u64 r; asm("mov.b64 %0, {%1, %2};" : "=l"(r) : "f"(lo), "f"(hi)); return r;
}
__device__ __forceinline__ void f2unpk(u64 v, float& lo, float& hi) {
    asm("mov.b64 {%0, %1}, %2;" : "=f"(lo), "=f"(hi) : "l"(v));
}
__device__ __forceinline__ u64 fma2(u64 a, u64 b, u64 c) {
    u64 r; asm("fma.rn.f32x2 %0, %1, %2, %3;" : "=l"(r) : "l"(a), "l"(b), "l"(c)); return r;
}
__device__ __forceinline__ u64 mul2(u64 a, u64 b) {
    u64 r; asm("mul.rn.f32x2 %0, %1, %2;" : "=l"(r) : "l"(a), "l"(b)); return r;
}
__device__ __forceinline__ u64 add2(u64 a, u64 b) {
    u64 r; asm("add.rn.f32x2 %0, %1, %2;" : "=l"(r) : "l"(a), "l"(b)); return r;
}

// ---- fp16x2 on u32 helpers ----
__device__ __forceinline__ u32 hfma2u(u32 a, u32 b, u32 c) {
    u32 r; asm("fma.rn.f16x2 %0, %1, %2, %3;" : "=r"(r) : "r"(a), "r"(b), "r"(c)); return r;
}
__device__ __forceinline__ u32 hmin2u(u32 a, u32 b) {
    u32 r; asm("min.f16x2 %0, %1, %2;" : "=r"(r) : "r"(a), "r"(b)); return r;
}
// per-lane mask: 0xFFFF where a==b (as f16), else 0
__device__ __forceinline__ u32 heq2mask(u32 a, u32 b) {
    u32 r; asm("set.eq.u32.f16x2 %0, %1, %2;" : "=r"(r) : "r"(a), "r"(b)); return r;
}
__device__ __forceinline__ u32 h2u(__half2 h) { return *reinterpret_cast<u32*>(&h); }

// MUFU-free packed sqrt: magic rsqrt seed + 2 Newton iters + x*r. x in [2e-6, ~13].
__device__ __forceinline__ u64 sqrt2_nomufu(u64 x, u64 C_H, u64 C_1p5) {
    float xl, xh;
    f2unpk(x, xl, xh);
    float rl = __int_as_float(0x5f3759df - (__float_as_int(xl) >> 1));
    float rh = __int_as_float(0x5f3759df - (__float_as_int(xh) >> 1));
    u64 r   = f2pk(rl, rh);
    u64 hxn = mul2(x, C_H);
    u64 m, u;
    m = mul2(r, r); u = fma2(hxn, m, C_1p5); r = mul2(r, u);
    m = mul2(r, r); u = fma2(hxn, m, C_1p5); r = mul2(r, u);
    return mul2(x, r);
}

__global__ __launch_bounds__(THREADS_, 8)
void nps_kernel(const float* __restrict__ adv,
                const float* __restrict__ prn,
                float* __restrict__ out)
{
    // fp16 weights per color: {W0h2, W1h2, W2h2, Ch2}, W=2*(1e-6-p) dup'd, C=sum v^2
    __shared__ uint4  shWC[30];
    // fp32 exact v per color: {v0, v1, v2, 0}
    __shared__ float4 shVC[30];
    __shared__ float  shRed[4];
    __shared__ int    shLast;

    int tid = threadIdx.x;
    if (tid < 30) {
        float v0 = 1e-6f - prn[tid * 3 + 0];
        float v1 = 1e-6f - prn[tid * 3 + 1];
        float v2 = 1e-6f - prn[tid * 3 + 2];
        float c  = v0 * v0 + v1 * v1 + v2 * v2;
        __half2 w0 = __float2half2_rn(2.f * v0);
        __half2 w1 = __float2half2_rn(2.f * v1);
        __half2 w2 = __float2half2_rn(2.f * v2);
        __half2 cc = __float2half2_rn(c);
        shWC[tid] = make_uint4(h2u(w0), h2u(w1), h2u(w2), h2u(cc));
        shVC[tid] = make_float4(v0, v1, v2, 0.f);
    }
    __syncthreads();

    // two float4-groups (8 pixels) per thread; stride NTHR_ groups for coalescing
    int tglob = blockIdx.x * THREADS_ + tid;
    float4 a0, a1, a2, b0, b1, b2;
    {
        int p4 = tglob * 4;
        const float4* q = reinterpret_cast<const float4*>(
            adv + (size_t)(p4 >> 18) * CHW_ + (p4 & (HW_ - 1)));
        a0 = q[0]; a1 = q[HW_ / 4]; a2 = q[2 * (HW_ / 4)];
    }
    {
        int p4 = (tglob + NTHR_) * 4;
        const float4* q = reinterpret_cast<const float4*>(
            adv + (size_t)(p4 >> 18) * CHW_ + (p4 & (HW_ - 1)));
        b0 = q[0]; b1 = q[HW_ / 4]; b2 = q[2 * (HW_ / 4)];
    }

    // fp16 pixel pairs as u32: [pair][channel]; A=(a0.x,a0.y) B=(a0.z,a0.w) C,D from group1
    u32 XA0 = h2u(__floats2half2_rn(a0.x, a0.y)), XA1 = h2u(__floats2half2_rn(a1.x, a1.y)),
        XA2 = h2u(__floats2half2_rn(a2.x, a2.y));
    u32 XB0 = h2u(__floats2half2_rn(a0.z, a0.w)), XB1 = h2u(__floats2half2_rn(a1.z, a1.w)),
        XB2 = h2u(__floats2half2_rn(a2.z, a2.w));
    u32 XC0 = h2u(__floats2half2_rn(b0.x, b0.y)), XC1 = h2u(__floats2half2_rn(b1.x, b1.y)),
        XC2 = h2u(__floats2half2_rn(b2.x, b2.y));
    u32 XD0 = h2u(__floats2half2_rn(b0.z, b0.w)), XD1 = h2u(__floats2half2_rn(b1.z, b1.w)),
        XD2 = h2u(__floats2half2_rn(b2.z, b2.w));

    u32 mA, mB, mC, mD;           // running fp16 min of acc (per lane)
    u32 idxA = 0, idxB = 0, idxC = 0, idxD = 0;   // packed 16-bit argmin
    {   // k = 0 peeled
        uint4 w = shWC[0];
        u32 t;
        t = hfma2u(w.x, XA0, w.w); t = hfma2u(w.y, XA1, t); mA = hfma2u(w.z, XA2, t);
        t = hfma2u(w.x, XB0, w.w); t = hfma2u(w.y, XB1, t); mB = hfma2u(w.z, XB2, t);
        t = hfma2u(w.x, XC0, w.w); t = hfma2u(w.y, XC1, t); mC = hfma2u(w.z, XC2, t);
        t = hfma2u(w.x, XD0, w.w); t = hfma2u(w.y, XD1, t); mD = hfma2u(w.z, XD2, t);
    }

    #pragma unroll 29
    for (int k = 1; k < 30; k++) {
        uint4 w = shWC[k];
        u32 kk = (u32)k | ((u32)k << 16);
        u32 t, mk;

        t = hfma2u(w.x, XA0, w.w); t = hfma2u(w.y, XA1, t); t = hfma2u(w.z, XA2, t);
        mA = hmin2u(mA, t); mk = heq2mask(t, mA);
        idxA = (mk & kk) | (idxA & ~mk);

        t = hfma2u(w.x, XB0, w.w); t = hfma2u(w.y, XB1, t); t = hfma2u(w.z, XB2, t);
        mB = hmin2u(mB, t); mk = heq2mask(t, mB);
        idxB = (mk & kk) | (idxB & ~mk);

        t = hfma2u(w.x, XC0, w.w); t = hfma2u(w.y, XC1, t); t = hfma2u(w.z, XC2, t);
        mC = hmin2u(mC, t); mk = heq2mask(t, mC);
        idxC = (mk & kk) | (idxC & ~mk);

        t = hfma2u(w.x, XD0, w.w); t = hfma2u(w.y, XD1, t); t = hfma2u(w.z, XD2, t);
        mD = hmin2u(mD, t); mk = heq2mask(t, mD);
        idxD = (mk & kk) | (idxD & ~mk);
    }

    // fp32 exact recompute of the winning color's distance (matches reference bit-path)
    float D0, D1, D2, D3, D4, D5, D6, D7;
    {
        float4 v; float d0, d1, d2;
        v = shVC[idxA & 0xFFFF];
        d0 = a0.x + v.x; d1 = a1.x + v.y; d2 = a2.x + v.z;
        D0 = fmaf(d0, d0, fmaf(d1, d1, fmaf(d2, d2, 1e-6f)));
        v = shVC[idxA >> 16];
        d0 = a0.y + v.x; d1 = a1.y + v.y; d2 = a2.y + v.z;
        D1 = fmaf(d0, d0, fmaf(d1, d1, fmaf(d2, d2, 1e-6f)));
        v = shVC[idxB & 0xFFFF];
        d0 = a0.z + v.x; d1 = a1.z + v.y; d2 = a2.z + v.z;
        D2 = fmaf(d0, d0, fmaf(d1, d1, fmaf(d2, d2, 1e-6f)));
        v = shVC[idxB >> 16];
        d0 = a0.w + v.x; d1 = a1.w + v.y; d2 = a2.w + v.z;
        D3 = fmaf(d0, d0, fmaf(d1, d1, fmaf(d2, d2, 1e-6f)));
        v = shVC[idxC & 0xFFFF];
        d0 = b0.x + v.x; d1 = b1.x + v.y; d2 = b2.x + v.z;
        D4 = fmaf(d0, d0, fmaf(d1, d1, fmaf(d2, d2, 1e-6f)));
        v = shVC[idxC >> 16];
        d0 = b0.y + v.x; d1 = b1.y + v.y; d2 = b2.y + v.z;
        D5 = fmaf(d0, d0, fmaf(d1, d1, fmaf(d2, d2, 1e-6f)));
        v = shVC[idxD & 0xFFFF];
        d0 = b0.z + v.x; d1 = b1.z + v.y; d2 = b2.z + v.z;
        D6 = fmaf(d0, d0, fmaf(d1, d1, fmaf(d2, d2, 1e-6f)));
        v = shVC[idxD >> 16];
        d0 = b0.w + v.x; d1 = b1.w + v.y; d2 = b2.w + v.z;
        D7 = fmaf(d0, d0, fmaf(d1, d1, fmaf(d2, d2, 1e-6f)));
    }

    const u64 C_H   = f2pk(-0.5f, -0.5f);
    const u64 C_1p5 = f2pk(1.5f, 1.5f);
    u64 qA = sqrt2_nomufu(f2pk(D0, D1), C_H, C_1p5);
    u64 qB = sqrt2_nomufu(f2pk(D2, D3), C_H, C_1p5);
    u64 qC = sqrt2_nomufu(f2pk(D4, D5), C_H, C_1p5);
    u64 qD = sqrt2_nomufu(f2pk(D6, D7), C_H, C_1p5);

    u64 ts = add2(add2(qA, qB), add2(qC, qD));
    float tl, th;
    f2unpk(ts, tl, th);
    float tsum = tl + th;

    // warp reduce
    #pragma unroll
    for (int off = 16; off > 0; off >>= 1)
        tsum += __shfl_xor_sync(0xffffffffu, tsum, off);
    if ((tid & 31) == 0) shRed[tid >> 5] = tsum;
    __syncthreads();

    if (tid == 0) {
        float bs = shRed[0] + shRed[1] + shRed[2] + shRed[3];
        g_partial[blockIdx.x] = bs;
        __threadfence();
        u32 prev = atomicInc(&g_count, BLOCKS_ - 1);
        shLast = (prev == BLOCKS_ - 1);
    }
    __syncthreads();

    if (shLast) {
        volatile float* vp = g_partial;
        float s = 0.0f;
        #pragma unroll
        for (int i = 0; i < BLOCKS_ / THREADS_; i++)
            s += vp[tid + i * THREADS_];
        #pragma unroll
        for (int off = 16; off > 0; off >>= 1)
            s += __shfl_xor_sync(0xffffffffu, s, off);
        if ((tid & 31) == 0) shRed[tid >> 5] = s;
        __syncthreads();
        if (tid == 0)
            out[0] = (shRed[0] + shRed[1] + shRed[2] + shRed[3]) * INV_SIZE_;
    }
}

extern "C" void kernel_launch(void* const* d_in, const int* in_sizes, int n_in,
                              void* d_out, int out_size)
{
    const float* adv = (const float*)d_in[0];   // (8,3,512,512) f32
    const float* prn = (const float*)d_in[1];   // (30,3) f32
    nps_kernel<<<BLOCKS_, THREADS_>>>(adv, prn, (float*)d_out);
}